// round 10
// baseline (speedup 1.0000x reference)
#include <cuda_runtime.h>
#include <math_constants.h>
#include <cstdint>

#define SS      128
#define BB      64
#define HH      512
#define VV      100
#define TSTEPS  31
#define NTH     256
#define NB      296     // 2 CTAs/SM x 148 SMs, single wave

// dynamic smem layout (floats):
#define SM_WLO   0
#define SM_WHI   8192
#define SM_STAGE 16384
#define SM_SYMS  (16384 + 2176)
#define SMEM_FLOATS (16384 + 2176 + 64)
#define SMEM_BYTES (SMEM_FLOATS * 4)

// ---------------- persistent scratch ----------------
__device__ float g_hT[2][HH * BB];       // hidden transposed [h][b]
__device__ float g_ctxT[HH * BB];        // context transposed
__device__ float g_ghp[4][3 * HH * BB];  // gh K-quarter partials [j][b]
__device__ float g_gip[4][3 * HH * BB];  // gi K-quarter partials [j][b]
__device__ float g_cp[8][HH * BB];       // comb partials: q=0..3 emb, 4..7 ctx
__device__ float g_lgp[4][VV * BB];      // logit K-quarter partials [v][b]
// epoch barrier (proven R9): distinct arrival slots + single release word
__device__ volatile unsigned g_arr[NB];
__device__ volatile unsigned g_rel;

__device__ __forceinline__ float warp_sum(float v) {
#pragma unroll
    for (int o = 16; o; o >>= 1) v += __shfl_xor_sync(0xffffffffu, v, o);
    return v;
}
__device__ __forceinline__ float warp_max(float v) {
#pragma unroll
    for (int o = 16; o; o >>= 1) v = fmaxf(v, __shfl_xor_sync(0xffffffffu, v, o));
    return v;
}
__device__ __forceinline__ float fast_tanh(float x) {
    float r;
    asm("tanh.approx.f32 %0, %1;" : "=f"(r) : "f"(x));
    return r;
}

__device__ __forceinline__ void gridbar(unsigned& ep) {
    __syncthreads();
    ep++;
    if (threadIdx.x == 0) {
        __threadfence();
        g_arr[blockIdx.x] = ep;
    }
    if (blockIdx.x == 0) {
        for (int i = threadIdx.x; i < NB; i += NTH) {
            while (g_arr[i] < ep) { __nanosleep(32); }
        }
        __syncthreads();
        if (threadIdx.x == 0) {
            __threadfence();
            g_rel = ep;
        }
    }
    if (threadIdx.x == 0) {
        while (g_rel < ep) { __nanosleep(32); }
        __threadfence();
    }
    __syncthreads();
}

// preload one 64-row x 128-col W tile into smem, k-major [k][64]
__device__ void preload_w(float* Wdst, const float* __restrict__ Wg, int ldw,
                          int row0, int rowlim, int col0)
{
    for (int f = threadIdx.x; f < 2048; f += NTH) {
        int j = f >> 5;
        int k4 = (f & 31) * 4;
        int row = row0 + j;
        if (row >= rowlim) row = rowlim - 1;
        float4 w = *(const float4*)(Wg + (size_t)row * ldw + col0 + k4);
        Wdst[(k4 + 0) * 64 + j] = w.x;
        Wdst[(k4 + 1) * 64 + j] = w.y;
        Wdst[(k4 + 2) * 64 + j] = w.z;
        Wdst[(k4 + 3) * 64 + j] = w.w;
    }
}

// ---------------------------------------------------------------------------
// GEMM job with resident W (proven R6/R9): C[64rows][64b], K=128 quarter.
// ---------------------------------------------------------------------------
__device__ void gemm64(float* smf, const float* Wres,
                       int j0, int rowlim, int mode,
                       const float* __restrict__ A0, int c0, int kq,
                       const int* __restrict__ tgt_t,
                       const float* __restrict__ b_comb,
                       float* __restrict__ Cout)
{
    const int tid = threadIdx.x;
    const int tx = tid & 15, ty = tid >> 4;
    float* Ash = smf + SM_STAGE;
    int* syms = (int*)(smf + SM_SYMS);

    float acc[4][4];
#pragma unroll
    for (int r = 0; r < 4; r++)
#pragma unroll
        for (int c = 0; c < 4; c++) acc[r][c] = 0.f;

    if (mode == 1) {
        if (tid < BB) syms[tid] = tgt_t[tid];
        __syncthreads();
    }

    float4 p0, p1;
    const int e = tid * 8;
    if (mode == 0) {
        p0 = __ldcg((const float4*)(A0 + e));
        p1 = __ldcg((const float4*)(A0 + e + 4));
    }

#pragma unroll 1
    for (int kc = 0; kc < 128; kc += 32) {
        if (mode == 0) {
            int k = e >> 6, b = e & 63;
            *(float4*)&Ash[k * 68 + b]     = p0;
            *(float4*)&Ash[k * 68 + b + 4] = p1;
        } else if (mode == 1) {
            int b = tid >> 2, kg = (tid & 3) * 8;
            const float* src = A0 + (size_t)syms[b] * HH + c0 + kc + kg;
            float4 v0 = *(const float4*)src;
            float4 v1 = *(const float4*)(src + 4);
            Ash[(kg + 0) * 68 + b] = v0.x; Ash[(kg + 1) * 68 + b] = v0.y;
            Ash[(kg + 2) * 68 + b] = v0.z; Ash[(kg + 3) * 68 + b] = v0.w;
            Ash[(kg + 4) * 68 + b] = v1.x; Ash[(kg + 5) * 68 + b] = v1.y;
            Ash[(kg + 6) * 68 + b] = v1.z; Ash[(kg + 7) * 68 + b] = v1.w;
        } else {
            int k = e >> 6, b = e & 63;
            size_t gx = (size_t)(kq * 128 + kc + k) * 64 + b;
            float bc = b_comb[kq * 128 + kc + k];
            float s0 = bc, s1 = bc, s2 = bc, s3 = bc;
            float s4 = bc, s5 = bc, s6 = bc, s7 = bc;
#pragma unroll
            for (int q = 0; q < 8; q++) {
                float4 u0 = __ldcg((const float4*)(g_cp[q] + gx));
                float4 u1 = __ldcg((const float4*)(g_cp[q] + gx + 4));
                s0 += u0.x; s1 += u0.y; s2 += u0.z; s3 += u0.w;
                s4 += u1.x; s5 += u1.y; s6 += u1.z; s7 += u1.w;
            }
            float* dst = &Ash[k * 68 + b];
            dst[0] = fmaxf(s0, 0.f); dst[1] = fmaxf(s1, 0.f);
            dst[2] = fmaxf(s2, 0.f); dst[3] = fmaxf(s3, 0.f);
            dst[4] = fmaxf(s4, 0.f); dst[5] = fmaxf(s5, 0.f);
            dst[6] = fmaxf(s6, 0.f); dst[7] = fmaxf(s7, 0.f);
        }
        __syncthreads();
        if (mode == 0 && kc + 32 < 128) {
            p0 = __ldcg((const float4*)(A0 + (kc + 32) * 64 + e));
            p1 = __ldcg((const float4*)(A0 + (kc + 32) * 64 + e + 4));
        }
#pragma unroll
        for (int k = 0; k < 32; k++) {
            float4 w4 = *(const float4*)&Wres[(kc + k) * 64 + tx * 4];
            float4 a4 = *(const float4*)&Ash[k * 68 + ty * 4];
            acc[0][0] = fmaf(w4.x, a4.x, acc[0][0]);
            acc[0][1] = fmaf(w4.x, a4.y, acc[0][1]);
            acc[0][2] = fmaf(w4.x, a4.z, acc[0][2]);
            acc[0][3] = fmaf(w4.x, a4.w, acc[0][3]);
            acc[1][0] = fmaf(w4.y, a4.x, acc[1][0]);
            acc[1][1] = fmaf(w4.y, a4.y, acc[1][1]);
            acc[1][2] = fmaf(w4.y, a4.z, acc[1][2]);
            acc[1][3] = fmaf(w4.y, a4.w, acc[1][3]);
            acc[2][0] = fmaf(w4.z, a4.x, acc[2][0]);
            acc[2][1] = fmaf(w4.z, a4.y, acc[2][1]);
            acc[2][2] = fmaf(w4.z, a4.z, acc[2][2]);
            acc[2][3] = fmaf(w4.z, a4.w, acc[2][3]);
            acc[3][0] = fmaf(w4.w, a4.x, acc[3][0]);
            acc[3][1] = fmaf(w4.w, a4.y, acc[3][1]);
            acc[3][2] = fmaf(w4.w, a4.z, acc[3][2]);
            acc[3][3] = fmaf(w4.w, a4.w, acc[3][3]);
        }
        __syncthreads();
    }
#pragma unroll
    for (int r = 0; r < 4; r++) {
        int row = j0 + tx * 4 + r;
        if (row < rowlim) {
            *(float4*)(Cout + (size_t)row * BB + ty * 4) =
                make_float4(acc[r][0], acc[r][1], acc[r][2], acc[r][3]);
        }
    }
}

// ---------------------------------------------------------------------------
// Bahdanau attention for batch element b. ctx loop: unroll 16, dual acc pairs.
// ---------------------------------------------------------------------------
__device__ void attention_block(float* smf, int b,
                                const float* __restrict__ enc,
                                const float* __restrict__ w_vat,
                                const float* __restrict__ b_vat,
                                const float* __restrict__ hT,
                                float* __restrict__ ctxT)
{
    float* sh_h = smf + SM_STAGE;
    float* sh_w = sh_h + HH;
    float* sh_sc = sh_w + HH;
    const int tid = threadIdx.x, wid = tid >> 5, lane = tid & 31;
    for (int i = tid; i < HH; i += NTH) {
        sh_h[i] = __ldcg(&hT[i * BB + b]);
        sh_w[i] = w_vat[i];
    }
    __syncthreads();
    const float bv = b_vat[0];
    const float4* hp = (const float4*)sh_h;
    const float4* wp = (const float4*)sh_w;
    for (int s = wid; s < SS; s += NTH / 32) {
        const float4* ep = (const float4*)(enc + ((size_t)s * BB + b) * HH);
        float acc = 0.f;
#pragma unroll
        for (int c = 0; c < 4; c++) {
            int k = lane + 32 * c;
            float4 e = ep[k], h4 = hp[k], w4 = wp[k];
            acc += fast_tanh(e.x + h4.x) * w4.x;
            acc += fast_tanh(e.y + h4.y) * w4.y;
            acc += fast_tanh(e.z + h4.z) * w4.z;
            acc += fast_tanh(e.w + h4.w) * w4.w;
        }
        acc = warp_sum(acc);
        if (lane == 0) sh_sc[s] = acc + bv;
    }
    __syncthreads();
    if (wid == 0) {
        float v0 = sh_sc[lane],      v1 = sh_sc[lane + 32];
        float v2 = sh_sc[lane + 64], v3 = sh_sc[lane + 96];
        float m = warp_max(fmaxf(fmaxf(v0, v1), fmaxf(v2, v3)));
        float e0 = expf(v0 - m), e1 = expf(v1 - m);
        float e2 = expf(v2 - m), e3 = expf(v3 - m);
        float inv = 1.f / warp_sum(e0 + e1 + e2 + e3);
        sh_sc[lane]      = e0 * inv; sh_sc[lane + 32] = e1 * inv;
        sh_sc[lane + 64] = e2 * inv; sh_sc[lane + 96] = e3 * inv;
    }
    __syncthreads();
    {
        // ctx[b, h0:h0+2] = sum_s attn[s]*enc[s,b,h0:h0+2]
        // unroll 16 -> MLP~16 to hide L2 latency; two acc pairs split the
        // FMA dependency chain.
        const int h0 = tid * 2;
        const float* base = enc + (size_t)b * HH + h0;
        float a0 = 0.f, a1 = 0.f, c0 = 0.f, c1 = 0.f;
#pragma unroll
        for (int s0 = 0; s0 < SS; s0 += 16) {
            float2 ev[16];
#pragma unroll
            for (int u = 0; u < 16; u++)
                ev[u] = *(const float2*)(base + (size_t)(s0 + u) * (BB * HH));
#pragma unroll
            for (int u = 0; u < 16; u += 2) {
                float w0 = sh_sc[s0 + u], w1 = sh_sc[s0 + u + 1];
                a0 = fmaf(w0, ev[u].x, a0);
                a1 = fmaf(w0, ev[u].y, a1);
                c0 = fmaf(w1, ev[u + 1].x, c0);
                c1 = fmaf(w1, ev[u + 1].y, c1);
            }
        }
        ctxT[h0 * BB + b]       = a0 + c0;
        ctxT[(h0 + 1) * BB + b] = a1 + c1;
    }
    __syncthreads();
}

// log-softmax for batch column b (one warp), summing 4 logit partials.
__device__ void lsm_row(int b, const float* __restrict__ b_out,
                        float* __restrict__ outp)
{
    const int lane = threadIdx.x & 31;
    float v0 = b_out[lane], v1 = b_out[lane + 32], v2 = b_out[lane + 64];
    bool ok3 = lane < (VV - 96);
    float v3 = ok3 ? b_out[lane + 96] : 0.f;
#pragma unroll
    for (int q = 0; q < 4; q++) {
        v0 += __ldcg(&g_lgp[q][lane * BB + b]);
        v1 += __ldcg(&g_lgp[q][(lane + 32) * BB + b]);
        v2 += __ldcg(&g_lgp[q][(lane + 64) * BB + b]);
        if (ok3) v3 += __ldcg(&g_lgp[q][(lane + 96) * BB + b]);
    }
    if (!ok3) v3 = -CUDART_INF_F;
    float m = warp_max(fmaxf(fmaxf(v0, v1), fmaxf(v2, v3)));
    float s = expf(v0 - m) + expf(v1 - m) + expf(v2 - m) + (ok3 ? expf(v3 - m) : 0.f);
    s = warp_sum(s);
    float lse = m + logf(s);
    outp[lane]      = v0 - lse;
    outp[lane + 32] = v1 - lse;
    outp[lane + 64] = v2 - lse;
    if (ok3) outp[lane + 96] = v3 - lse;
}

// CTA map (SM s hosts bids s and s+148):
//   0-63    : attention (PA, partners 148-211 idle in PA); lsm on 0-7 (PB)
//   64-147  : gh g=bid-64          (PA) | gi same g (PC)
//   212-223 : gh g=84+(bid-212)    (PA) | gi same g (PC)
//   224-255 : comb-emb g=bid-224   (PA) | comb-ctx same g (PB)
//   256-263 : logits g=bid-256     (PA, t>=1; + final)
__global__ void __launch_bounds__(NTH, 2)
bahdanau_kernel(
    const float* __restrict__ enc,    const float* __restrict__ W_emb,
    const float* __restrict__ W_comb, const float* __restrict__ b_comb,
    const float* __restrict__ W_ih,   const float* __restrict__ W_hh,
    const float* __restrict__ b_ih,   const float* __restrict__ b_hh,
    const float* __restrict__ W_out,  const float* __restrict__ b_out,
    const float* __restrict__ w_vat,  const float* __restrict__ b_vat,
    const int* __restrict__ tgt, float* __restrict__ out)
{
    extern __shared__ float smf[];
    const int bid = blockIdx.x;
    const int tid = threadIdx.x;
    const int wid = tid >> 5;

    unsigned ep = g_rel;   // persisted epoch base (0 on first launch)

    // ---- one-time W preload ----
    if (bid >= 64 && bid < 148) {
        int g = bid - 64, mt = g >> 2, kq = g & 3;
        preload_w(smf + SM_WLO, W_hh, HH, mt * 64, 3 * HH, kq * 128);
        preload_w(smf + SM_WHI, W_ih, HH, mt * 64, 3 * HH, kq * 128);
    } else if (bid >= 212 && bid < 224) {
        int g = 84 + (bid - 212), mt = g >> 2, kq = g & 3;
        preload_w(smf + SM_WLO, W_hh, HH, mt * 64, 3 * HH, kq * 128);
        preload_w(smf + SM_WHI, W_ih, HH, mt * 64, 3 * HH, kq * 128);
    } else if (bid >= 224 && bid < 256) {
        int g = bid - 224, mt = g >> 2, kq = g & 3;
        preload_w(smf + SM_WLO, W_comb, 2 * HH, mt * 64, HH, kq * 128);
        preload_w(smf + SM_WHI, W_comb, 2 * HH, mt * 64, HH, HH + kq * 128);
    } else if (bid >= 256 && bid < 264) {
        int g = bid - 256, lt = g >> 2, kq = g & 3;
        preload_w(smf + SM_WLO, W_out, HH, lt * 64, VV, kq * 128);
    }
    for (int i = bid * NTH + tid; i < HH * BB; i += NB * NTH) g_hT[0][i] = 0.f;
    gridbar(ep);

    for (int t = 0; t < TSTEPS; t++) {
        const float* hcur = g_hT[t & 1];
        float* hnext = g_hT[(t + 1) & 1];

        // === PA: attention | gh | comb-emb | logits(prev h) ===
        if (bid < BB) {
            attention_block(smf, bid, enc, w_vat, b_vat, hcur, g_ctxT);
        } else if (bid >= 64 && bid < 148) {
            int g = bid - 64, mt = g >> 2, kq = g & 3;
            gemm64(smf, smf + SM_WLO, mt * 64, 3 * HH, 0,
                   hcur + kq * 128 * BB, 0, kq, nullptr, nullptr, g_ghp[kq]);
        } else if (bid >= 212 && bid < 224) {
            int g = 84 + (bid - 212), mt = g >> 2, kq = g & 3;
            gemm64(smf, smf + SM_WLO, mt * 64, 3 * HH, 0,
                   hcur + kq * 128 * BB, 0, kq, nullptr, nullptr, g_ghp[kq]);
        } else if (bid >= 224 && bid < 256) {
            int g = bid - 224, mt = g >> 2, kq = g & 3;
            gemm64(smf, smf + SM_WLO, mt * 64, HH, 1,
                   W_emb, kq * 128, kq, tgt + t * BB, nullptr, g_cp[kq]);
        } else if (bid >= 256 && bid < 264) {
            if (t >= 1) {
                int g = bid - 256, lt = g >> 2, kq = g & 3;
                gemm64(smf, smf + SM_WLO, lt * 64, VV, 0,
                       hcur + kq * 128 * BB, 0, kq, nullptr, nullptr, g_lgp[kq]);
            }
        }
        gridbar(ep);

        // === PB: comb-ctx (224-255, solo SMs) | lsm prev (0-7) ===
        if (bid >= 224 && bid < 256) {
            int g = bid - 224, mt = g >> 2, kq = g & 3;
            gemm64(smf, smf + SM_WHI, mt * 64, HH, 0,
                   g_ctxT + kq * 128 * BB, 0, kq, nullptr, nullptr, g_cp[4 + kq]);
        } else if (bid < 8) {
            if (t >= 1) {
                int b = bid * 8 + wid;
                lsm_row(b, b_out, out + (size_t)b * TSTEPS * VV + (size_t)(t - 1) * VV);
            }
        }
        gridbar(ep);

        // === PC: gi (64-147, 212-223) ===
        if (bid >= 64 && bid < 148) {
            int g = bid - 64, mt = g >> 2, kq = g & 3;
            gemm64(smf, smf + SM_WHI, mt * 64, 3 * HH, 2,
                   nullptr, 0, kq, nullptr, b_comb, g_gip[kq]);
        } else if (bid >= 212 && bid < 224) {
            int g = 84 + (bid - 212), mt = g >> 2, kq = g & 3;
            gemm64(smf, smf + SM_WHI, mt * 64, 3 * HH, 2,
                   nullptr, 0, kq, nullptr, b_comb, g_gip[kq]);
        }
        gridbar(ep);

        // === PD: GRU gates elementwise ===
        {
            int e = bid * NTH + tid;
            if (e < HH * BB) {
                int i = e >> 6, b = e & 63;
                size_t ir = (size_t)i * BB + b;
                size_t iz = (size_t)(i + HH) * BB + b;
                size_t in_ = (size_t)(i + 2 * HH) * BB + b;
                float gir = b_ih[i], giz = b_ih[i + HH], gin = b_ih[i + 2 * HH];
                float ghr = b_hh[i], ghz = b_hh[i + HH], ghn = b_hh[i + 2 * HH];
#pragma unroll
                for (int q = 0; q < 4; q++) {
                    gir += __ldcg(&g_gip[q][ir]);
                    giz += __ldcg(&g_gip[q][iz]);
                    gin += __ldcg(&g_gip[q][in_]);
                    ghr += __ldcg(&g_ghp[q][ir]);
                    ghz += __ldcg(&g_ghp[q][iz]);
                    ghn += __ldcg(&g_ghp[q][in_]);
                }
                float ho = __ldcg(&hcur[ir]);
                float r = 1.f / (1.f + expf(-(gir + ghr)));
                float z = 1.f / (1.f + expf(-(giz + ghz)));
                float n = tanhf(gin + r * ghn);
                hnext[ir] = (1.f - z) * n + z * ho;
            }
        }
        gridbar(ep);
    }

    // ===== final logits (slot TSTEPS-1) =====
    const float* hfin = g_hT[TSTEPS & 1];
    if (bid >= 256 && bid < 264) {
        int g = bid - 256, lt = g >> 2, kq = g & 3;
        gemm64(smf, smf + SM_WLO, lt * 64, VV, 0,
               hfin + kq * 128 * BB, 0, kq, nullptr, nullptr, g_lgp[kq]);
    }
    gridbar(ep);
    if (bid < 8) {
        int b = bid * 8 + wid;
        lsm_row(b, b_out, out + (size_t)b * TSTEPS * VV + (size_t)(TSTEPS - 1) * VV);
    }
}

extern "C" void kernel_launch(void* const* d_in, const int* in_sizes, int n_in,
                              void* d_out, int out_size) {
    const float* enc    = (const float*)d_in[0];
    const float* W_emb  = (const float*)d_in[1];
    const float* W_comb = (const float*)d_in[2];
    const float* b_comb = (const float*)d_in[3];
    const float* W_ih   = (const float*)d_in[4];
    const float* W_hh   = (const float*)d_in[5];
    const float* b_ih   = (const float*)d_in[6];
    const float* b_hh   = (const float*)d_in[7];
    const float* W_out  = (const float*)d_in[8];
    const float* b_out  = (const float*)d_in[9];
    const float* w_vat  = (const float*)d_in[10];
    const float* b_vat  = (const float*)d_in[11];
    const int*   tgt    = (const int*)d_in[12];
    float* out = (float*)d_out;

    cudaFuncSetAttribute(bahdanau_kernel,
                         cudaFuncAttributeMaxDynamicSharedMemorySize, SMEM_BYTES);
    bahdanau_kernel<<<NB, NTH, SMEM_BYTES>>>(enc, W_emb, W_comb, b_comb,
                                             W_ih, W_hh, b_ih, b_hh,
                                             W_out, b_out, w_vat, b_vat,
                                             tgt, out);
}

// round 11
// speedup vs baseline: 1.0798x; 1.0798x over previous
#include <cuda_runtime.h>
#include <math_constants.h>
#include <cstdint>

#define SS      128
#define BB      64
#define HH      512
#define VV      100
#define TSTEPS  31
#define NTH     256
#define NB      296     // 2 CTAs/SM x 148 SMs, single wave

// dynamic smem layout (floats):
#define SM_WLO   0
#define SM_WHI   8192
#define SM_STAGE 16384
#define SM_SYMS  (16384 + 2176)
#define SMEM_FLOATS (16384 + 2176 + 64)
#define SMEM_BYTES (SMEM_FLOATS * 4)

// ---------------- persistent scratch ----------------
__device__ float g_hT[2][HH * BB];        // hidden transposed [h][b]
__device__ float g_ctxT[HH * BB];         // context transposed
__device__ float g_ghp[4][3 * HH * BB];   // gh K-quarter partials [j][b]
__device__ float g_gip[4][3 * HH * BB];   // gi K-quarter partials [j][b]
__device__ float g_cctx[4][HH * BB];      // comb-ctx K-quarter partials
__device__ float g_cemb[TSTEPS * 4 * HH * BB];  // comb-emb partials, all steps
__device__ float g_lgp[2][4][VV * BB];    // logit partials, parity-buffered
// epoch barrier (proven R9): distinct arrival slots + single release word
__device__ volatile unsigned g_arr[NB];
__device__ volatile unsigned g_rel;

__device__ __forceinline__ float warp_sum(float v) {
#pragma unroll
    for (int o = 16; o; o >>= 1) v += __shfl_xor_sync(0xffffffffu, v, o);
    return v;
}
__device__ __forceinline__ float warp_max(float v) {
#pragma unroll
    for (int o = 16; o; o >>= 1) v = fmaxf(v, __shfl_xor_sync(0xffffffffu, v, o));
    return v;
}
__device__ __forceinline__ float fast_tanh(float x) {
    float r;
    asm("tanh.approx.f32 %0, %1;" : "=f"(r) : "f"(x));
    return r;
}

__device__ __forceinline__ void gridbar(unsigned& ep) {
    __syncthreads();
    ep++;
    if (threadIdx.x == 0) {
        __threadfence();
        g_arr[blockIdx.x] = ep;
    }
    if (blockIdx.x == 0) {
        for (int i = threadIdx.x; i < NB; i += NTH) {
            while (g_arr[i] < ep) { __nanosleep(32); }
        }
        __syncthreads();
        if (threadIdx.x == 0) {
            __threadfence();
            g_rel = ep;
        }
    }
    if (threadIdx.x == 0) {
        while (g_rel < ep) { __nanosleep(32); }
        __threadfence();
    }
    __syncthreads();
}

// preload one 64-row x 128-col W tile into smem, k-major [k][64]
__device__ void preload_w(float* Wdst, const float* __restrict__ Wg, int ldw,
                          int row0, int rowlim, int col0)
{
    for (int f = threadIdx.x; f < 2048; f += NTH) {
        int j = f >> 5;
        int k4 = (f & 31) * 4;
        int row = row0 + j;
        if (row >= rowlim) row = rowlim - 1;
        float4 w = *(const float4*)(Wg + (size_t)row * ldw + col0 + k4);
        Wdst[(k4 + 0) * 64 + j] = w.x;
        Wdst[(k4 + 1) * 64 + j] = w.y;
        Wdst[(k4 + 2) * 64 + j] = w.z;
        Wdst[(k4 + 3) * 64 + j] = w.w;
    }
}

// ---------------------------------------------------------------------------
// GEMM job with resident W (proven R6/R9): C[64rows][64b], K=128 quarter.
// mode 0: A0 transposed activation (pre-offset), ldcg + register prefetch
// mode 1: A[k][b] = W_emb[syms[b]][c0+k]
// mode 2: A[k][b] = relu( sum_q (A0[q][..] + g_cctx[q][..]) + b_comb[..] ),
//         A0 = per-step comb-emb partial base (4 quarters of [512][64])
// ---------------------------------------------------------------------------
__device__ void gemm64(float* smf, const float* Wres,
                       int j0, int rowlim, int mode,
                       const float* __restrict__ A0, int c0, int kq,
                       const int* __restrict__ tgt_t,
                       const float* __restrict__ b_comb,
                       float* __restrict__ Cout)
{
    const int tid = threadIdx.x;
    const int tx = tid & 15, ty = tid >> 4;
    float* Ash = smf + SM_STAGE;
    int* syms = (int*)(smf + SM_SYMS);

    float acc[4][4];
#pragma unroll
    for (int r = 0; r < 4; r++)
#pragma unroll
        for (int c = 0; c < 4; c++) acc[r][c] = 0.f;

    if (mode == 1) {
        if (tid < BB) syms[tid] = tgt_t[tid];
        __syncthreads();
    }

    float4 p0, p1;
    const int e = tid * 8;
    if (mode == 0) {
        p0 = __ldcg((const float4*)(A0 + e));
        p1 = __ldcg((const float4*)(A0 + e + 4));
    }

#pragma unroll 1
    for (int kc = 0; kc < 128; kc += 32) {
        if (mode == 0) {
            int k = e >> 6, b = e & 63;
            *(float4*)&Ash[k * 68 + b]     = p0;
            *(float4*)&Ash[k * 68 + b + 4] = p1;
        } else if (mode == 1) {
            int b = tid >> 2, kg = (tid & 3) * 8;
            const float* src = A0 + (size_t)syms[b] * HH + c0 + kc + kg;
            float4 v0 = *(const float4*)src;
            float4 v1 = *(const float4*)(src + 4);
            Ash[(kg + 0) * 68 + b] = v0.x; Ash[(kg + 1) * 68 + b] = v0.y;
            Ash[(kg + 2) * 68 + b] = v0.z; Ash[(kg + 3) * 68 + b] = v0.w;
            Ash[(kg + 4) * 68 + b] = v1.x; Ash[(kg + 5) * 68 + b] = v1.y;
            Ash[(kg + 6) * 68 + b] = v1.z; Ash[(kg + 7) * 68 + b] = v1.w;
        } else {
            int k = e >> 6, b = e & 63;
            size_t gx = (size_t)(kq * 128 + kc + k) * 64 + b;
            float bc = b_comb[kq * 128 + kc + k];
            float s0 = bc, s1 = bc, s2 = bc, s3 = bc;
            float s4 = bc, s5 = bc, s6 = bc, s7 = bc;
#pragma unroll
            for (int q = 0; q < 4; q++) {
                float4 u0 = __ldcg((const float4*)(A0 + (size_t)q * (HH * BB) + gx));
                float4 u1 = __ldcg((const float4*)(A0 + (size_t)q * (HH * BB) + gx + 4));
                float4 v0 = __ldcg((const float4*)(g_cctx[q] + gx));
                float4 v1 = __ldcg((const float4*)(g_cctx[q] + gx + 4));
                s0 += u0.x + v0.x; s1 += u0.y + v0.y;
                s2 += u0.z + v0.z; s3 += u0.w + v0.w;
                s4 += u1.x + v1.x; s5 += u1.y + v1.y;
                s6 += u1.z + v1.z; s7 += u1.w + v1.w;
            }
            float* dst = &Ash[k * 68 + b];
            dst[0] = fmaxf(s0, 0.f); dst[1] = fmaxf(s1, 0.f);
            dst[2] = fmaxf(s2, 0.f); dst[3] = fmaxf(s3, 0.f);
            dst[4] = fmaxf(s4, 0.f); dst[5] = fmaxf(s5, 0.f);
            dst[6] = fmaxf(s6, 0.f); dst[7] = fmaxf(s7, 0.f);
        }
        __syncthreads();
        if (mode == 0 && kc + 32 < 128) {
            p0 = __ldcg((const float4*)(A0 + (kc + 32) * 64 + e));
            p1 = __ldcg((const float4*)(A0 + (kc + 32) * 64 + e + 4));
        }
#pragma unroll
        for (int k = 0; k < 32; k++) {
            float4 w4 = *(const float4*)&Wres[(kc + k) * 64 + tx * 4];
            float4 a4 = *(const float4*)&Ash[k * 68 + ty * 4];
            acc[0][0] = fmaf(w4.x, a4.x, acc[0][0]);
            acc[0][1] = fmaf(w4.x, a4.y, acc[0][1]);
            acc[0][2] = fmaf(w4.x, a4.z, acc[0][2]);
            acc[0][3] = fmaf(w4.x, a4.w, acc[0][3]);
            acc[1][0] = fmaf(w4.y, a4.x, acc[1][0]);
            acc[1][1] = fmaf(w4.y, a4.y, acc[1][1]);
            acc[1][2] = fmaf(w4.y, a4.z, acc[1][2]);
            acc[1][3] = fmaf(w4.y, a4.w, acc[1][3]);
            acc[2][0] = fmaf(w4.z, a4.x, acc[2][0]);
            acc[2][1] = fmaf(w4.z, a4.y, acc[2][1]);
            acc[2][2] = fmaf(w4.z, a4.z, acc[2][2]);
            acc[2][3] = fmaf(w4.z, a4.w, acc[2][3]);
            acc[3][0] = fmaf(w4.w, a4.x, acc[3][0]);
            acc[3][1] = fmaf(w4.w, a4.y, acc[3][1]);
            acc[3][2] = fmaf(w4.w, a4.z, acc[3][2]);
            acc[3][3] = fmaf(w4.w, a4.w, acc[3][3]);
        }
        __syncthreads();
    }
#pragma unroll
    for (int r = 0; r < 4; r++) {
        int row = j0 + tx * 4 + r;
        if (row < rowlim) {
            *(float4*)(Cout + (size_t)row * BB + ty * 4) =
                make_float4(acc[r][0], acc[r][1], acc[r][2], acc[r][3]);
        }
    }
}

// ---------------------------------------------------------------------------
// Bahdanau attention for batch element b (proven R3/R6; ctx loop from R10).
// ---------------------------------------------------------------------------
__device__ void attention_block(float* smf, int b,
                                const float* __restrict__ enc,
                                const float* __restrict__ w_vat,
                                const float* __restrict__ b_vat,
                                const float* __restrict__ hT,
                                float* __restrict__ ctxT)
{
    float* sh_h = smf + SM_STAGE;
    float* sh_w = sh_h + HH;
    float* sh_sc = sh_w + HH;
    const int tid = threadIdx.x, wid = tid >> 5, lane = tid & 31;
    for (int i = tid; i < HH; i += NTH) {
        sh_h[i] = __ldcg(&hT[i * BB + b]);
        sh_w[i] = w_vat[i];
    }
    __syncthreads();
    const float bv = b_vat[0];
    const float4* hp = (const float4*)sh_h;
    const float4* wp = (const float4*)sh_w;
    for (int s = wid; s < SS; s += NTH / 32) {
        const float4* ep = (const float4*)(enc + ((size_t)s * BB + b) * HH);
        float acc = 0.f;
#pragma unroll
        for (int c = 0; c < 4; c++) {
            int k = lane + 32 * c;
            float4 e = ep[k], h4 = hp[k], w4 = wp[k];
            acc += fast_tanh(e.x + h4.x) * w4.x;
            acc += fast_tanh(e.y + h4.y) * w4.y;
            acc += fast_tanh(e.z + h4.z) * w4.z;
            acc += fast_tanh(e.w + h4.w) * w4.w;
        }
        acc = warp_sum(acc);
        if (lane == 0) sh_sc[s] = acc + bv;
    }
    __syncthreads();
    if (wid == 0) {
        float v0 = sh_sc[lane],      v1 = sh_sc[lane + 32];
        float v2 = sh_sc[lane + 64], v3 = sh_sc[lane + 96];
        float m = warp_max(fmaxf(fmaxf(v0, v1), fmaxf(v2, v3)));
        float e0 = expf(v0 - m), e1 = expf(v1 - m);
        float e2 = expf(v2 - m), e3 = expf(v3 - m);
        float inv = 1.f / warp_sum(e0 + e1 + e2 + e3);
        sh_sc[lane]      = e0 * inv; sh_sc[lane + 32] = e1 * inv;
        sh_sc[lane + 64] = e2 * inv; sh_sc[lane + 96] = e3 * inv;
    }
    __syncthreads();
    {
        const int h0 = tid * 2;
        const float* base = enc + (size_t)b * HH + h0;
        float a0 = 0.f, a1 = 0.f, c0 = 0.f, c1 = 0.f;
#pragma unroll
        for (int s0 = 0; s0 < SS; s0 += 16) {
            float2 ev[16];
#pragma unroll
            for (int u = 0; u < 16; u++)
                ev[u] = *(const float2*)(base + (size_t)(s0 + u) * (BB * HH));
#pragma unroll
            for (int u = 0; u < 16; u += 2) {
                float w0 = sh_sc[s0 + u], w1 = sh_sc[s0 + u + 1];
                a0 = fmaf(w0, ev[u].x, a0);
                a1 = fmaf(w0, ev[u].y, a1);
                c0 = fmaf(w1, ev[u + 1].x, c0);
                c1 = fmaf(w1, ev[u + 1].y, c1);
            }
        }
        ctxT[h0 * BB + b]       = a0 + c0;
        ctxT[(h0 + 1) * BB + b] = a1 + c1;
    }
    __syncthreads();
}

// log-softmax for column b (one warp); lg = parity base, 4 quarter partials.
__device__ void lsm_row(const float* __restrict__ lg, int b,
                        const float* __restrict__ b_out,
                        float* __restrict__ outp)
{
    const int lane = threadIdx.x & 31;
    float v0 = b_out[lane], v1 = b_out[lane + 32], v2 = b_out[lane + 64];
    bool ok3 = lane < (VV - 96);
    float v3 = ok3 ? b_out[lane + 96] : 0.f;
#pragma unroll
    for (int q = 0; q < 4; q++) {
        const float* lq = lg + (size_t)q * (VV * BB);
        v0 += __ldcg(&lq[lane * BB + b]);
        v1 += __ldcg(&lq[(lane + 32) * BB + b]);
        v2 += __ldcg(&lq[(lane + 64) * BB + b]);
        if (ok3) v3 += __ldcg(&lq[(lane + 96) * BB + b]);
    }
    if (!ok3) v3 = -CUDART_INF_F;
    float m = warp_max(fmaxf(fmaxf(v0, v1), fmaxf(v2, v3)));
    float s = expf(v0 - m) + expf(v1 - m) + expf(v2 - m) + (ok3 ? expf(v3 - m) : 0.f);
    s = warp_sum(s);
    float lse = m + logf(s);
    outp[lane]      = v0 - lse;
    outp[lane + 32] = v1 - lse;
    outp[lane + 64] = v2 - lse;
    if (ok3) outp[lane + 96] = v3 - lse;
}

// CTA map:
//   0-63    : attention (PA)
//   64-147  : gh g=bid-64 (PA) | gi g=bid-64 (PC)
//   148-159 : comb-ctx g=bid-148 (PB) | gi g=84+(bid-148) (PC)
//   160-179 : comb-ctx g=bid-148 (PB)
//   180-187 : logits (PB; + tail)
//   188-199 : gh-late g=84+(bid-188) (PB)
//   200-207 : lsm (PB t>=2; + tail)
__global__ void __launch_bounds__(NTH, 2)
bahdanau_kernel(
    const float* __restrict__ enc,    const float* __restrict__ W_emb,
    const float* __restrict__ W_comb, const float* __restrict__ b_comb,
    const float* __restrict__ W_ih,   const float* __restrict__ W_hh,
    const float* __restrict__ b_ih,   const float* __restrict__ b_hh,
    const float* __restrict__ W_out,  const float* __restrict__ b_out,
    const float* __restrict__ w_vat,  const float* __restrict__ b_vat,
    const int* __restrict__ tgt, float* __restrict__ out)
{
    extern __shared__ float smf[];
    const int bid = blockIdx.x;
    const int tid = threadIdx.x;
    const int wid = tid >> 5;

    unsigned ep = g_rel;   // persisted epoch base

    // ---- prologue: comb-emb for ALL steps (992 quarter-jobs) ----
    for (int jj = bid; jj < TSTEPS * 32; jj += NB) {
        int t = jj >> 5, g = jj & 31, mt = g >> 2, kq = g & 3;
        preload_w(smf + SM_WLO, W_comb, 2 * HH, mt * 64, HH, kq * 128);
        __syncthreads();
        gemm64(smf, smf + SM_WLO, mt * 64, HH, 1,
               W_emb, kq * 128, kq, tgt + t * BB, nullptr,
               g_cemb + ((size_t)(t * 4 + kq)) * (HH * BB));
        __syncthreads();
    }

    // ---- steady-state W preload ----
    if (bid >= 64 && bid < 148) {
        int g = bid - 64;
        int mt = g >> 2, kq = g & 3;
        preload_w(smf + SM_WLO, W_hh, HH, mt * 64, 3 * HH, kq * 128);
        preload_w(smf + SM_WHI, W_ih, HH, mt * 64, 3 * HH, kq * 128);
    } else if (bid >= 148 && bid < 160) {
        int gc = bid - 148, gi_ = 84 + (bid - 148);
        preload_w(smf + SM_WLO, W_comb, 2 * HH, (gc >> 2) * 64, HH,
                  HH + (gc & 3) * 128);
        preload_w(smf + SM_WHI, W_ih, HH, (gi_ >> 2) * 64, 3 * HH,
                  (gi_ & 3) * 128);
    } else if (bid >= 160 && bid < 180) {
        int gc = bid - 148;
        preload_w(smf + SM_WLO, W_comb, 2 * HH, (gc >> 2) * 64, HH,
                  HH + (gc & 3) * 128);
    } else if (bid >= 180 && bid < 188) {
        int g = bid - 180, lt = g >> 2, kq = g & 3;
        preload_w(smf + SM_WLO, W_out, HH, lt * 64, VV, kq * 128);
    } else if (bid >= 188 && bid < 200) {
        int g = 84 + (bid - 188), mt = g >> 2, kq = g & 3;
        preload_w(smf + SM_WLO, W_hh, HH, mt * 64, 3 * HH, kq * 128);
    }
    for (int i = bid * NTH + tid; i < HH * BB; i += NB * NTH) g_hT[0][i] = 0.f;
    gridbar(ep);

    for (int t = 0; t < TSTEPS; t++) {
        const float* hcur = g_hT[t & 1];
        float* hnext = g_hT[(t + 1) & 1];

        // === PA: attention (0-63) | gh g=0..83 (64-147): 1 job per SM ===
        if (bid < BB) {
            attention_block(smf, bid, enc, w_vat, b_vat, hcur, g_ctxT);
        } else if (bid >= 64 && bid < 148) {
            int g = bid - 64, mt = g >> 2, kq = g & 3;
            gemm64(smf, smf + SM_WLO, mt * 64, 3 * HH, 0,
                   hcur + kq * 128 * BB, 0, kq, nullptr, nullptr, g_ghp[kq]);
        }
        gridbar(ep);

        // === PB: comb-ctx | logits | gh-late | lsm (all solo SMs) ===
        if (bid >= 148 && bid < 180) {
            int g = bid - 148, mt = g >> 2, kq = g & 3;
            gemm64(smf, smf + SM_WLO, mt * 64, HH, 0,
                   g_ctxT + kq * 128 * BB, 0, kq, nullptr, nullptr, g_cctx[kq]);
        } else if (bid >= 180 && bid < 188) {
            if (t >= 1) {
                int g = bid - 180, lt = g >> 2, kq = g & 3;
                gemm64(smf, smf + SM_WLO, lt * 64, VV, 0,
                       hcur + kq * 128 * BB, 0, kq, nullptr, nullptr,
                       g_lgp[t & 1][kq]);
            }
        } else if (bid >= 188 && bid < 200) {
            int g = 84 + (bid - 188), mt = g >> 2, kq = g & 3;
            gemm64(smf, smf + SM_WLO, mt * 64, 3 * HH, 0,
                   hcur + kq * 128 * BB, 0, kq, nullptr, nullptr, g_ghp[kq]);
        } else if (bid >= 200 && bid < 208) {
            if (t >= 2) {
                int b = (bid - 200) * 8 + wid;
                lsm_row(&g_lgp[(t - 1) & 1][0][0], b, b_out,
                        out + (size_t)b * TSTEPS * VV + (size_t)(t - 2) * VV);
            }
        }
        gridbar(ep);

        // === PC: gi 96 jobs (64-159, all solo) ===
        if (bid >= 64 && bid < 160) {
            int g = (bid < 148) ? (bid - 64) : (84 + (bid - 148));
            int mt = g >> 2, kq = g & 3;
            gemm64(smf, smf + SM_WHI, mt * 64, 3 * HH, 2,
                   g_cemb + (size_t)t * 4 * (HH * BB), 0, kq,
                   nullptr, b_comb, g_gip[kq]);
        }
        gridbar(ep);

        // === PD: GRU gates elementwise ===
        {
            int e = bid * NTH + tid;
            if (e < HH * BB) {
                int i = e >> 6, b = e & 63;
                size_t ir = (size_t)i * BB + b;
                size_t iz = (size_t)(i + HH) * BB + b;
                size_t in_ = (size_t)(i + 2 * HH) * BB + b;
                float gir = b_ih[i], giz = b_ih[i + HH], gin = b_ih[i + 2 * HH];
                float ghr = b_hh[i], ghz = b_hh[i + HH], ghn = b_hh[i + 2 * HH];
#pragma unroll
                for (int q = 0; q < 4; q++) {
                    gir += __ldcg(&g_gip[q][ir]);
                    giz += __ldcg(&g_gip[q][iz]);
                    gin += __ldcg(&g_gip[q][in_]);
                    ghr += __ldcg(&g_ghp[q][ir]);
                    ghz += __ldcg(&g_ghp[q][iz]);
                    ghn += __ldcg(&g_ghp[q][in_]);
                }
                float ho = __ldcg(&hcur[ir]);
                float r = 1.f / (1.f + expf(-(gir + ghr)));
                float z = 1.f / (1.f + expf(-(giz + ghz)));
                float n = tanhf(gin + r * ghn);
                hnext[ir] = (1.f - z) * n + z * ho;
            }
        }
        gridbar(ep);
    }

    // ===== tail: slot 29 lsm (parity 0) + final logits h_31 (parity 1) =====
    const float* hfin = g_hT[TSTEPS & 1];
    if (bid >= 180 && bid < 188) {
        int g = bid - 180, lt = g >> 2, kq = g & 3;
        gemm64(smf, smf + SM_WLO, lt * 64, VV, 0,
               hfin + kq * 128 * BB, 0, kq, nullptr, nullptr, g_lgp[1][kq]);
    } else if (bid >= 200 && bid < 208) {
        int b = (bid - 200) * 8 + wid;
        lsm_row(&g_lgp[0][0][0], b, b_out,
                out + (size_t)b * TSTEPS * VV + (size_t)(TSTEPS - 2) * VV);
    }
    gridbar(ep);
    if (bid >= 200 && bid < 208) {
        int b = (bid - 200) * 8 + wid;
        lsm_row(&g_lgp[1][0][0], b, b_out,
                out + (size_t)b * TSTEPS * VV + (size_t)(TSTEPS - 1) * VV);
    }
}

extern "C" void kernel_launch(void* const* d_in, const int* in_sizes, int n_in,
                              void* d_out, int out_size) {
    const float* enc    = (const float*)d_in[0];
    const float* W_emb  = (const float*)d_in[1];
    const float* W_comb = (const float*)d_in[2];
    const float* b_comb = (const float*)d_in[3];
    const float* W_ih   = (const float*)d_in[4];
    const float* W_hh   = (const float*)d_in[5];
    const float* b_ih   = (const float*)d_in[6];
    const float* b_hh   = (const float*)d_in[7];
    const float* W_out  = (const float*)d_in[8];
    const float* b_out  = (const float*)d_in[9];
    const float* w_vat  = (const float*)d_in[10];
    const float* b_vat  = (const float*)d_in[11];
    const int*   tgt    = (const int*)d_in[12];
    float* out = (float*)d_out;

    cudaFuncSetAttribute(bahdanau_kernel,
                         cudaFuncAttributeMaxDynamicSharedMemorySize, SMEM_BYTES);
    bahdanau_kernel<<<NB, NTH, SMEM_BYTES>>>(enc, W_emb, W_comb, b_comb,
                                             W_ih, W_hh, b_ih, b_hh,
                                             W_out, b_out, w_vat, b_vat,
                                             tgt, out);
}